// round 2
// baseline (speedup 1.0000x reference)
#include <cuda_runtime.h>

#define B   32
#define C   512
#define HW  1024
#define T   1025
#define NH  8
#define CH  64
#define SCALE2 0.125f   // (1/64^{0.25})^2 = 1/8

// Scratch (allocation-free requirement -> __device__ globals)
__device__ float g_m[B * C];            // spatial means
__device__ float g_qw[B * NH * C];      // folded query-weight: scale^2 * q0^T W_k
__device__ float g_qb[B * NH];          // scale^2 * q0 . b_k (constant per row; kept for exactness)
__device__ float g_p[B * NH * T];       // logits -> probabilities (in place)
__device__ float g_y[B * NH * C];       // prob-weighted xf sums

// ---------------------------------------------------------------------------
// K1: per-(b,c) spatial mean over 1024 elements. 1 block per row, float4 loads.
__global__ void k_mean(const float* __restrict__ x) {
    int row = blockIdx.x;                       // 0..B*C-1
    const float4* p = (const float4*)(x + (size_t)row * HW);
    float4 v = p[threadIdx.x];                  // 256 threads * 4 = 1024
    float s = v.x + v.y + v.z + v.w;
    __shared__ float red[256];
    red[threadIdx.x] = s;
    __syncthreads();
    for (int o = 128; o; o >>= 1) {
        if (threadIdx.x < o) red[threadIdx.x] += red[threadIdx.x + o];
        __syncthreads();
    }
    if (threadIdx.x == 0) g_m[row] = red[0] * (1.0f / HW);
}

// ---------------------------------------------------------------------------
// K2: per batch, compute x0 = mean + pos_emb[:,0], q0 = W_q x0 + b_q (scaled),
//     qw[h,ci] = sum_ch q0s[h,ch] * W_k[h*64+ch, ci],  qb[h] = q0s . b_k
__global__ void k_qw(const float* __restrict__ pos,
                     const float* __restrict__ wqkv,
                     const float* __restrict__ bqkv) {
    int b = blockIdx.x;
    int tid = threadIdx.x;
    __shared__ float x0[C];
    __shared__ float q0[C];
    for (int c = tid; c < C; c += 256) x0[c] = g_m[b * C + c] + pos[(size_t)c * T];
    __syncthreads();
    for (int o = tid; o < C; o += 256) {
        const float* wr = wqkv + (size_t)o * C;
        float s = bqkv[o];
        #pragma unroll 8
        for (int c = 0; c < C; c++) s += wr[c] * x0[c];
        q0[o] = s * SCALE2;
    }
    __syncthreads();
    for (int idx = tid; idx < NH * C; idx += 256) {
        int h = idx >> 9;           // /512
        int ci = idx & (C - 1);
        const float* wk = wqkv + ((size_t)(C + h * CH)) * C + ci;
        float s = 0.0f;
        #pragma unroll 8
        for (int ch = 0; ch < CH; ch++) s += q0[h * CH + ch] * wk[(size_t)ch * C];
        g_qw[(size_t)b * NH * C + idx] = s;
    }
    if (tid < NH) {
        int h = tid;
        float s = 0.0f;
        for (int ch = 0; ch < CH; ch++) s += q0[h * CH + ch] * bqkv[C + h * CH + ch];
        g_qb[b * NH + h] = s;
    }
}

// ---------------------------------------------------------------------------
// K3: logits[b,h,t] = qb[b,h] + sum_ci qw[b,h,ci] * xf[b,ci,t]
//     xf[b,ci,0] = mean + pos ; xf[b,ci,t>0] = x[b,ci,t-1] + pos
//     grid (ceil(T/128), B), block 128; thread owns one t, 8 head-accumulators.
__global__ void k_logits(const float* __restrict__ x, const float* __restrict__ pos) {
    int b = blockIdx.y;
    int t = blockIdx.x * 128 + threadIdx.x;
    __shared__ float sqw[NH * C];               // 16 KB
    for (int i = threadIdx.x; i < NH * C; i += 128)
        sqw[i] = g_qw[(size_t)b * NH * C + i];
    __syncthreads();
    if (t >= T) return;

    float acc[NH];
    #pragma unroll
    for (int h = 0; h < NH; h++) acc[h] = 0.0f;

    if (t == 0) {
        for (int ci = 0; ci < C; ci++) {
            float v = g_m[b * C + ci] + pos[(size_t)ci * T];
            #pragma unroll
            for (int h = 0; h < NH; h++) acc[h] += sqw[h * C + ci] * v;
        }
    } else {
        const float* xp = x + (size_t)b * C * HW + (t - 1);
        #pragma unroll 4
        for (int ci = 0; ci < C; ci++) {
            float v = xp[(size_t)ci * HW] + pos[(size_t)ci * T + t];
            #pragma unroll
            for (int h = 0; h < NH; h++) acc[h] += sqw[h * C + ci] * v;
        }
    }
    #pragma unroll
    for (int h = 0; h < NH; h++)
        g_p[((size_t)b * NH + h) * T + t] = acc[h] + g_qb[b * NH + h];
}

// ---------------------------------------------------------------------------
// K4: softmax over T per (b,h) row, in place in g_p.
__global__ void k_softmax() {
    int row = blockIdx.x;                       // 0..B*NH-1
    float* p = g_p + (size_t)row * T;
    int tid = threadIdx.x;
    __shared__ float red[256];

    float m = -1e30f;
    for (int t = tid; t < T; t += 256) m = fmaxf(m, p[t]);
    red[tid] = m;
    __syncthreads();
    for (int o = 128; o; o >>= 1) {
        if (tid < o) red[tid] = fmaxf(red[tid], red[tid + o]);
        __syncthreads();
    }
    float M = red[0];
    __syncthreads();

    float s = 0.0f;
    for (int t = tid; t < T; t += 256) {
        float e = expf(p[t] - M);
        p[t] = e;
        s += e;
    }
    red[tid] = s;
    __syncthreads();
    for (int o = 128; o; o >>= 1) {
        if (tid < o) red[tid] += red[tid + o];
        __syncthreads();
    }
    float inv = 1.0f / red[0];
    for (int t = tid; t < T; t += 256) p[t] *= inv;
}

// ---------------------------------------------------------------------------
// K5: y[b,h,ci] = sum_t p[b,h,t] * xf[b,ci,t]
//     grid (C/8, B), block 256 = 8 warps; warp owns one ci, lanes split t.
__global__ void k_y(const float* __restrict__ x, const float* __restrict__ pos) {
    int b = blockIdx.y;
    int warp = threadIdx.x >> 5, lane = threadIdx.x & 31;
    int ci = blockIdx.x * 8 + warp;
    __shared__ float sp[NH * T];                // 32.8 KB
    for (int i = threadIdx.x; i < NH * T; i += 256)
        sp[i] = g_p[(size_t)b * NH * T + i];
    __syncthreads();

    const float* xr = x + ((size_t)b * C + ci) * HW;
    const float* per = pos + (size_t)ci * T;
    float acc[NH];
    #pragma unroll
    for (int h = 0; h < NH; h++) acc[h] = 0.0f;

    for (int t = 1 + lane; t < T; t += 32) {
        float v = xr[t - 1] + per[t];
        #pragma unroll
        for (int h = 0; h < NH; h++) acc[h] += sp[h * T + t] * v;
    }
    if (lane == 0) {                            // t = 0 (mean token)
        float v = g_m[b * C + ci] + per[0];
        #pragma unroll
        for (int h = 0; h < NH; h++) acc[h] += sp[h * T] * v;
    }
    #pragma unroll
    for (int h = 0; h < NH; h++) {
        float v = acc[h];
        for (int off = 16; off; off >>= 1) v += __shfl_down_sync(0xffffffffu, v, off);
        if (lane == 0) g_y[((size_t)b * NH + h) * C + ci] = v;
    }
}

// ---------------------------------------------------------------------------
// K6: attn_out[b,c] = b_v[c] + W_v[c,:] . y[b, c/64, :]
//     out[b,o]      = b_c[o] + W_c[o,:] . attn_out[b,:]
__global__ void k_out(const float* __restrict__ wqkv,
                      const float* __restrict__ bqkv,
                      const float* __restrict__ wc,
                      const float* __restrict__ bc,
                      float* __restrict__ out) {
    int b = blockIdx.x, tid = threadIdx.x;
    __shared__ float sy[NH * C];
    __shared__ float sa[C];
    for (int i = tid; i < NH * C; i += 256) sy[i] = g_y[(size_t)b * NH * C + i];
    __syncthreads();
    for (int c = tid; c < C; c += 256) {
        int h = c >> 6;
        const float* wv = wqkv + (size_t)(2 * C + c) * C;
        float s = bqkv[2 * C + c];               // b_v[c]; softmax weights sum to 1
        #pragma unroll 8
        for (int ci = 0; ci < C; ci++) s += wv[ci] * sy[h * C + ci];
        sa[c] = s;
    }
    __syncthreads();
    for (int o = tid; o < C; o += 256) {
        const float* w = wc + (size_t)o * C;
        float s = bc[o];
        #pragma unroll 8
        for (int c = 0; c < C; c++) s += w[c] * sa[c];
        out[(size_t)b * C + o] = s;
    }
}

// ---------------------------------------------------------------------------
extern "C" void kernel_launch(void* const* d_in, const int* in_sizes, int n_in,
                              void* d_out, int out_size) {
    const float* x    = (const float*)d_in[0];
    const float* pos  = (const float*)d_in[1];
    const float* wqkv = (const float*)d_in[2];
    const float* bqkv = (const float*)d_in[3];
    const float* wc   = (const float*)d_in[4];
    const float* bc   = (const float*)d_in[5];
    float* out = (float*)d_out;

    k_mean<<<B * C, 256>>>(x);
    k_qw<<<B, 256>>>(pos, wqkv, bqkv);
    dim3 g3((T + 127) / 128, B);
    k_logits<<<g3, 128>>>(x, pos);
    k_softmax<<<B * NH, 256>>>();
    dim3 g5(C / 8, B);
    k_y<<<g5, 256>>>(x, pos);
    k_out<<<B, 256>>>(wqkv, bqkv, wc, bc, out);
}

// round 3
// speedup vs baseline: 4.9542x; 4.9542x over previous
#include <cuda_runtime.h>

#define B   32
#define C   512
#define HW  1024
#define T   1025
#define NH  8
#define CH  64
#define SCALE2 0.125f   // (1/64^{0.25})^2 = 1/8

// ---------------------------------------------------------------------------
// Scratch (allocation-free rules -> __device__ globals)
__device__ float g_m  [B * C];          // spatial means
__device__ float g_x0 [B * C];          // mean-token input: mean + pos[:,0]
__device__ float g_q0 [B * C];          // scaled q at t=0: 0.125*(W_q x0 + b_q)
__device__ float g_qw [B * NH * C];     // folded query weight: q0s^T W_k
__device__ float g_p  [B * NH * T];     // logits
__device__ float g_ps [B * NH * HW];    // probs, shifted: [row][t-1]
__device__ float g_p0 [B * NH];         // prob at t=0
__device__ float g_y  [B * NH * C];     // prob-weighted xf sums
__device__ float g_a  [B * C];          // attn output (pre out-proj)

__device__ __forceinline__ float wred(float v) {
    #pragma unroll
    for (int o = 16; o; o >>= 1) v += __shfl_down_sync(0xffffffffu, v, o);
    return v;
}

// ---------------------------------------------------------------------------
// K1: per-(b,c) spatial mean; also emit x0 = mean + pos[c,0].
__global__ void k_mean(const float* __restrict__ x, const float* __restrict__ pos) {
    int row = blockIdx.x;                           // b*C + c
    int tid = threadIdx.x, warp = tid >> 5, lane = tid & 31;
    const float4* p = (const float4*)(x + (size_t)row * HW);
    float4 v = p[tid];
    float s = wred(v.x + v.y + v.z + v.w);
    __shared__ float red[8];
    if (lane == 0) red[warp] = s;
    __syncthreads();
    if (tid == 0) {
        float t = red[0] + red[1] + red[2] + red[3] + red[4] + red[5] + red[6] + red[7];
        float m = t * (1.0f / HW);
        g_m[row] = m;
        int c = row & (C - 1);
        g_x0[row] = m + pos[(size_t)c * T];
    }
}

// ---------------------------------------------------------------------------
// K2: q0s[b,o] = 0.125*(b_q[o] + W_q[o,:] . x0[b,:]).  Warp per (b,o).
__global__ void k_q0(const float* __restrict__ wqkv, const float* __restrict__ bqkv) {
    int warp = threadIdx.x >> 5, lane = threadIdx.x & 31;
    int idx = blockIdx.x * 8 + warp;                // 0..B*C-1
    int b = idx >> 9, o = idx & (C - 1);
    const float4* w = (const float4*)(wqkv + (size_t)o * C);
    const float4* xv = (const float4*)(g_x0 + (size_t)b * C);
    float acc = 0.0f;
    #pragma unroll
    for (int k = 0; k < 4; k++) {
        int i = lane + 32 * k;
        float4 a = w[i], c = xv[i];
        acc += a.x * c.x + a.y * c.y + a.z * c.z + a.w * c.w;
    }
    acc = wred(acc);
    if (lane == 0) g_q0[(size_t)b * C + o] = SCALE2 * (acc + bqkv[o]);
}

// ---------------------------------------------------------------------------
// K3: qw[b,h,ci] = sum_ch q0s[b,h*64+ch] * W_k[h*64+ch, ci].  Thread per output.
__global__ void k_qw(const float* __restrict__ wqkv) {
    int t = blockIdx.x * 256 + threadIdx.x;         // 0..B*NH*C-1
    int b = t >> 12, rem = t & 4095, h = rem >> 9, ci = rem & (C - 1);
    const float* wk = wqkv + ((size_t)(C + h * CH)) * C + ci;
    const float* q  = g_q0 + (size_t)b * C + h * CH;
    float acc = 0.0f;
    #pragma unroll 8
    for (int ch = 0; ch < CH; ch++) acc += q[ch] * wk[(size_t)ch * C];
    g_qw[(size_t)b * NH * C + rem] = acc;
}

// ---------------------------------------------------------------------------
// K4: logit at t=0.  Warp per (b,h).
__global__ void k_logit0() {
    int b = blockIdx.x, h = threadIdx.x >> 5, lane = threadIdx.x & 31;
    float acc = 0.0f;
    #pragma unroll
    for (int k = 0; k < 16; k++) {
        int ci = lane + 32 * k;
        acc += g_qw[(size_t)b * NH * C + h * C + ci] * g_x0[(size_t)b * C + ci];
    }
    acc = wred(acc);
    if (lane == 0) g_p[((size_t)b * NH + h) * T] = acc;
}

// ---------------------------------------------------------------------------
// K5: logits for t=1..1024.  Block = 256 t's; smem-tiled, double-buffered.
__global__ void k_logits(const float* __restrict__ x, const float* __restrict__ pos) {
    __shared__ float sqw[NH * C];                   // transposed: [ci*8 + h]
    __shared__ float tile[2][16 * 256];
    int b = blockIdx.y, tid = threadIdx.x;
    int tm1 = blockIdx.x * 256 + tid;               // t-1 in 0..1023
    for (int i = tid; i < NH * C; i += 256) {
        int h = i >> 9, ci = i & (C - 1);
        sqw[ci * 8 + h] = g_qw[(size_t)b * NH * C + i];
    }
    const float* xb = x + ((size_t)b * C) * HW + tm1;
    const float* pb = pos + tm1 + 1;

    float v[16];
    #pragma unroll
    for (int r = 0; r < 16; r++)
        v[r] = xb[(size_t)r * HW] + pb[(size_t)r * T];

    float acc[8] = {0, 0, 0, 0, 0, 0, 0, 0};
    int buf = 0;
    for (int c0 = 0; c0 < C; c0 += 16) {
        float* tb = tile[buf];
        #pragma unroll
        for (int r = 0; r < 16; r++) tb[r * 256 + tid] = v[r];
        __syncthreads();
        if (c0 + 16 < C) {
            const float* xn = xb + (size_t)(c0 + 16) * HW;
            const float* pn = pb + (size_t)(c0 + 16) * T;
            #pragma unroll
            for (int r = 0; r < 16; r++)
                v[r] = xn[(size_t)r * HW] + pn[(size_t)r * T];
        }
        #pragma unroll
        for (int r = 0; r < 16; r++) {
            float xv = tb[r * 256 + tid];
            const float4* w = (const float4*)&sqw[(c0 + r) * 8];
            float4 w0 = w[0], w1 = w[1];
            acc[0] += w0.x * xv; acc[1] += w0.y * xv;
            acc[2] += w0.z * xv; acc[3] += w0.w * xv;
            acc[4] += w1.x * xv; acc[5] += w1.y * xv;
            acc[6] += w1.z * xv; acc[7] += w1.w * xv;
        }
        buf ^= 1;
    }
    #pragma unroll
    for (int h = 0; h < 8; h++)
        g_p[((size_t)b * NH + h) * T + tm1 + 1] = acc[h];
}

// ---------------------------------------------------------------------------
// K6: softmax over T, single pass (5 regs/thread), emits shifted probs.
__global__ void k_softmax() {
    int row = blockIdx.x, tid = threadIdx.x, warp = tid >> 5, lane = tid & 31;
    const float* p = g_p + (size_t)row * T;
    __shared__ float red[8];
    float v[5];
    #pragma unroll
    for (int k = 0; k < 5; k++) {
        int t = tid + k * 256;
        v[k] = (t < T) ? p[t] : -1e30f;
    }
    float m = v[0];
    #pragma unroll
    for (int k = 1; k < 5; k++) m = fmaxf(m, v[k]);
    #pragma unroll
    for (int o = 16; o; o >>= 1) m = fmaxf(m, __shfl_down_sync(0xffffffffu, m, o));
    if (lane == 0) red[warp] = m;
    __syncthreads();
    float M = red[0];
    #pragma unroll
    for (int w = 1; w < 8; w++) M = fmaxf(M, red[w]);
    __syncthreads();

    float s = 0.0f;
    #pragma unroll
    for (int k = 0; k < 5; k++) { v[k] = __expf(v[k] - M); s += v[k]; }
    s = wred(s);
    if (lane == 0) red[warp] = s;
    __syncthreads();
    float S = red[0] + red[1] + red[2] + red[3] + red[4] + red[5] + red[6] + red[7];
    float inv = 1.0f / S;
    #pragma unroll
    for (int k = 0; k < 5; k++) {
        int t = tid + k * 256;
        if (t == 0)      g_p0[row] = v[k] * inv;
        else if (t < T)  g_ps[(size_t)row * HW + t - 1] = v[k] * inv;
    }
}

// ---------------------------------------------------------------------------
// K7: y[b,h,ci] = sum_t p[b,h,t]*xf[b,ci,t].  Warp per ci, float4 loads.
__global__ void k_y(const float* __restrict__ x, const float* __restrict__ pos) {
    __shared__ float sp[NH * HW];                   // shifted probs, 32 KB
    __shared__ float sp0[NH];
    int b = blockIdx.y, tid = threadIdx.x, warp = tid >> 5, lane = tid & 31;
    {
        const float4* src = (const float4*)(g_ps + (size_t)b * NH * HW);
        float4* dst = (float4*)sp;
        for (int i = tid; i < NH * HW / 4; i += 256) dst[i] = src[i];
        if (tid < NH) sp0[tid] = g_p0[b * NH + tid];
    }
    __syncthreads();

    int ci = blockIdx.x * 8 + warp;
    const float4* xr = (const float4*)(x + ((size_t)b * C + ci) * HW);
    const float*  pp = pos + (size_t)ci * T;
    float acc[8] = {0, 0, 0, 0, 0, 0, 0, 0};
    #pragma unroll
    for (int k = 0; k < 8; k++) {
        int i4 = lane + 32 * k;
        float4 xv = xr[i4];
        int tb = 4 * i4;
        float v0 = xv.x + pp[tb + 1];
        float v1 = xv.y + pp[tb + 2];
        float v2 = xv.z + pp[tb + 3];
        float v3 = xv.w + pp[tb + 4];
        #pragma unroll
        for (int h = 0; h < 8; h++) {
            float4 pv = ((const float4*)sp)[h * (HW / 4) + i4];
            acc[h] += pv.x * v0 + pv.y * v1 + pv.z * v2 + pv.w * v3;
        }
    }
    if (lane == 0) {
        float v = g_x0[(size_t)b * C + ci];
        #pragma unroll
        for (int h = 0; h < 8; h++) acc[h] += sp0[h] * v;
    }
    #pragma unroll
    for (int h = 0; h < 8; h++) {
        float r = wred(acc[h]);
        if (lane == 0) g_y[((size_t)b * NH + h) * C + ci] = r;
    }
}

// ---------------------------------------------------------------------------
// K8: attn[b,c] = b_v[c] + W_v[c,:] . y[b, c/64, :].  Warp per (b,c).
__global__ void k_attn(const float* __restrict__ wqkv, const float* __restrict__ bqkv) {
    int warp = threadIdx.x >> 5, lane = threadIdx.x & 31;
    int idx = blockIdx.x * 8 + warp;
    int b = idx >> 9, c = idx & (C - 1), h = c >> 6;
    const float4* w = (const float4*)(wqkv + (size_t)(2 * C + c) * C);
    const float4* y = (const float4*)(g_y + (size_t)b * NH * C + h * C);
    float acc = 0.0f;
    #pragma unroll
    for (int k = 0; k < 4; k++) {
        int i = lane + 32 * k;
        float4 a = w[i], d = y[i];
        acc += a.x * d.x + a.y * d.y + a.z * d.z + a.w * d.w;
    }
    acc = wred(acc);
    if (lane == 0) g_a[(size_t)b * C + c] = acc + bqkv[2 * C + c];
}

// ---------------------------------------------------------------------------
// K9: out[b,o] = b_c[o] + W_c[o,:] . attn[b,:].  Warp per (b,o).
__global__ void k_out(const float* __restrict__ wc, const float* __restrict__ bc,
                      float* __restrict__ out) {
    int warp = threadIdx.x >> 5, lane = threadIdx.x & 31;
    int idx = blockIdx.x * 8 + warp;
    int b = idx >> 9, o = idx & (C - 1);
    const float4* w = (const float4*)(wc + (size_t)o * C);
    const float4* a = (const float4*)(g_a + (size_t)b * C);
    float acc = 0.0f;
    #pragma unroll
    for (int k = 0; k < 4; k++) {
        int i = lane + 32 * k;
        float4 u = w[i], d = a[i];
        acc += u.x * d.x + u.y * d.y + u.z * d.z + u.w * d.w;
    }
    acc = wred(acc);
    if (lane == 0) out[(size_t)b * C + o] = acc + bc[o];
}

// ---------------------------------------------------------------------------
extern "C" void kernel_launch(void* const* d_in, const int* in_sizes, int n_in,
                              void* d_out, int out_size) {
    const float* x    = (const float*)d_in[0];
    const float* pos  = (const float*)d_in[1];
    const float* wqkv = (const float*)d_in[2];
    const float* bqkv = (const float*)d_in[3];
    const float* wc   = (const float*)d_in[4];
    const float* bc   = (const float*)d_in[5];
    float* out = (float*)d_out;

    k_mean  <<<B * C, 256>>>(x, pos);
    k_q0    <<<B * C / 8, 256>>>(wqkv, bqkv);
    k_qw    <<<B * NH * C / 256, 256>>>(wqkv);
    k_logit0<<<B, 256>>>();
    dim3 gl(4, B);
    k_logits<<<gl, 256>>>(x, pos);
    k_softmax<<<B * NH, 256>>>();
    dim3 gy(C / 8, B);
    k_y     <<<gy, 256>>>(x, pos);
    k_attn  <<<B * C / 8, 256>>>(wqkv, bqkv);
    k_out   <<<B * C / 8, 256>>>(wc, bc, out);
}